// round 3
// baseline (speedup 1.0000x reference)
#include <cuda_runtime.h>
#include <cstdint>
#include <cstddef>

// Problem dims (fixed per reference)
#define BB_ 2048
#define NN_ 64
#define CC_ 256
#define FF_ 256
#define NEGV (-9.0e15f)

// -------- scratch (allocation-free: __device__ globals) --------
__device__ float g_H1[BB_ * NN_ * FF_];      // 134 MB: h1 = x@W1, layout [(b*64+m), f]
__device__ float g_adj[FF_ * NN_ * NN_];     // 4 MB: full softmax adj [f][n][m]
__device__ float g_d[FF_ * NN_];             // diag adj[f][n][n], layout [f][n]
__device__ float g_Wcat[CC_ * 2 * FF_];      // [c][0:256)=W1, [256:512)=W0-W1
__device__ int   g_mask_mode;                // 0=uint8, 1=int32, 2=float32

// -------- helpers --------
__device__ __forceinline__ uint32_t f2t(float x) {
    uint32_t r;
    asm("cvt.rna.tf32.f32 %0, %1;" : "=r"(r) : "f"(x));
    return r;
}

__device__ __forceinline__ void mma8(float* d, const uint32_t* a, const uint32_t* b) {
    asm volatile(
        "mma.sync.aligned.m16n8k8.row.col.f32.tf32.tf32.f32 "
        "{%0,%1,%2,%3}, {%4,%5,%6,%7}, {%8,%9}, {%0,%1,%2,%3};\n"
        : "+f"(d[0]), "+f"(d[1]), "+f"(d[2]), "+f"(d[3])
        : "r"(a[0]), "r"(a[1]), "r"(a[2]), "r"(a[3]), "r"(b[0]), "r"(b[1]));
}

// single extern dynamic-smem symbol, used by k_gemm and k_einsum
extern __shared__ float sm_dyn[];

// -------- kernel 0: detect mask dtype --------
// Reads the first 1024 int32 words (4096 bytes: in-bounds whether mask is
// bool [4096 B], int32 [16 KB], or f32 [16 KB]).
__global__ void k_detect(const int* __restrict__ m) {
    int all01 = 1, allf = 1;
    for (int i = threadIdx.x; i < 1024; i += 32) {
        int v = m[i];
        if (!(v == 0 || v == 1)) all01 = 0;
        if (!(v == 0 || v == 0x3F800000)) allf = 0;
    }
    #pragma unroll
    for (int s = 16; s > 0; s >>= 1) {
        all01 &= __shfl_xor_sync(0xffffffffu, all01, s);
        allf  &= __shfl_xor_sync(0xffffffffu, allf, s);
    }
    if (threadIdx.x == 0) g_mask_mode = all01 ? 1 : (allf ? 2 : 0);
}

// -------- kernel 1: build Wcat = [W1 | W0 - W1] --------
__global__ void k_prep(const float* __restrict__ W) {
    int i = blockIdx.x * 256 + threadIdx.x;     // 131072 = 256*512
    int c = i >> 9, n = i & 511;
    float v;
    if (n < 256) {
        v = W[CC_ * FF_ + c * 256 + n];                           // W1
    } else {
        int f = n - 256;
        v = W[c * 256 + f] - W[CC_ * FF_ + c * 256 + f];          // W0 - W1
    }
    g_Wcat[c * 512 + n] = v;
}

// -------- kernel 2: masked row-softmax of e -> adj, diag -> d --------
// one warp per (f,n) row of 64
__global__ void k_softmax(const float* __restrict__ e, const void* __restrict__ maskp) {
    int w = threadIdx.x >> 5, lane = threadIdx.x & 31;
    int row = blockIdx.x * 8 + w;               // 0..16383 (= f*64+n)
    int n = row & 63;

    int mode = g_mask_mode;
    bool m0, m1;
    if (mode == 1) {
        const int* mi = (const int*)maskp;
        m0 = mi[n * 64 + lane] != 0;
        m1 = mi[n * 64 + lane + 32] != 0;
    } else if (mode == 2) {
        const float* mf = (const float*)maskp;
        m0 = mf[n * 64 + lane] != 0.0f;
        m1 = mf[n * 64 + lane + 32] != 0.0f;
    } else {
        const unsigned char* mb = (const unsigned char*)maskp;
        m0 = mb[n * 64 + lane] != 0;
        m1 = mb[n * 64 + lane + 32] != 0;
    }

    const float* er = e + (size_t)row * 64;
    float v0 = m0 ? er[lane] : NEGV;
    float v1 = m1 ? er[lane + 32] : NEGV;

    float mx = fmaxf(v0, v1);
    #pragma unroll
    for (int s = 16; s > 0; s >>= 1) mx = fmaxf(mx, __shfl_xor_sync(0xffffffff, mx, s));

    float e0 = expf(v0 - mx);   // masked -> exp(-9e15 - mx) == 0 exactly
    float e1 = expf(v1 - mx);
    float sum = e0 + e1;
    #pragma unroll
    for (int s = 16; s > 0; s >>= 1) sum += __shfl_xor_sync(0xffffffff, sum, s);
    float inv = 1.0f / sum;

    float a0 = e0 * inv, a1 = e1 * inv;
    g_adj[(size_t)row * 64 + lane] = a0;
    g_adj[(size_t)row * 64 + lane + 32] = a1;
    if (lane == n)      g_d[row] = a0;
    if (lane + 32 == n) g_d[row] = a1;
}

// -------- kernel 3: tf32 GEMM  Y = X[131072,256] @ Wcat[256,512] --------
// by==0: cols 0..255  -> H1 scratch
// by==1: cols 256..511 -> out = d[f,n]*(h0-h1) + bias[f]
// CTA tile: BM=64, BN=256, BK=16; 8 warps (2 M x 4 N), warp tile 32x64
#define GEMM_AS_ELEMS (2 * 16 * 68)
#define GEMM_BS_ELEMS (2 * 16 * 260)
#define GEMM_SMEM ((GEMM_AS_ELEMS + GEMM_BS_ELEMS) * 4)

__global__ __launch_bounds__(256) void k_gemm(const float* __restrict__ X,
                                              const float* __restrict__ bias,
                                              float* __restrict__ out) {
    uint32_t* As = (uint32_t*)sm_dyn;                   // [buf][k][m]: buf*16*68 + k*68 + m
    uint32_t* Bs = (uint32_t*)sm_dyn + GEMM_AS_ELEMS;   // [buf][k][n]: buf*16*260 + k*260 + n

    const int t = threadIdx.x, lane = t & 31, w = t >> 5;
    const int wm = w & 1, wn = w >> 1;
    const int rowBase = blockIdx.x * 64;
    const int nBase = blockIdx.y * 256;

    const int ar = t >> 2, akq = (t & 3) * 4;         // A loader: row ar, k-quad
    const int bkr = t >> 4, bnq = (t & 15) * 16;      // B loader: row bkr, 16 cols
    const float* gA = X + (size_t)(rowBase + ar) * 256 + akq;
    const float* gB = g_Wcat + (size_t)bkr * 512 + nBase + bnq;

    float acc[2][8][4];
    #pragma unroll
    for (int i = 0; i < 2; i++)
        #pragma unroll
        for (int j = 0; j < 8; j++)
            #pragma unroll
            for (int r = 0; r < 4; r++) acc[i][j][r] = 0.0f;

    float4 va;
    float4 vb[4];

    // prefetch stage 0
    va = *(const float4*)(gA + 0);
    #pragma unroll
    for (int j = 0; j < 4; j++) vb[j] = *(const float4*)(gB + j * 4);

    // store stage 0
    {
        As[(akq + 0) * 68 + ar] = f2t(va.x);
        As[(akq + 1) * 68 + ar] = f2t(va.y);
        As[(akq + 2) * 68 + ar] = f2t(va.z);
        As[(akq + 3) * 68 + ar] = f2t(va.w);
        #pragma unroll
        for (int j = 0; j < 4; j++) {
            uint4 u;
            u.x = f2t(vb[j].x); u.y = f2t(vb[j].y);
            u.z = f2t(vb[j].z); u.w = f2t(vb[j].w);
            *(uint4*)&Bs[bkr * 260 + bnq + j * 4] = u;
        }
    }
    __syncthreads();

    #pragma unroll 1
    for (int kt = 0; kt < 16; kt++) {
        int buf = kt & 1;
        uint32_t* Ab = As + buf * (16 * 68);
        uint32_t* Bb = Bs + buf * (16 * 260);
        if (kt < 15) {
            int k0 = (kt + 1) * 16;
            va = *(const float4*)(gA + k0);
            #pragma unroll
            for (int j = 0; j < 4; j++)
                vb[j] = *(const float4*)(gB + (size_t)k0 * 512 + j * 4);
        }
        #pragma unroll
        for (int ks = 0; ks < 2; ks++) {
            int kk = ks * 8 + (lane & 3);
            uint32_t af[2][4];
            #pragma unroll
            for (int mt = 0; mt < 2; mt++) {
                int m = wm * 32 + mt * 16 + (lane >> 2);
                af[mt][0] = Ab[kk * 68 + m];
                af[mt][1] = Ab[kk * 68 + m + 8];
                af[mt][2] = Ab[(kk + 4) * 68 + m];
                af[mt][3] = Ab[(kk + 4) * 68 + m + 8];
            }
            #pragma unroll
            for (int nt = 0; nt < 8; nt++) {
                int n = wn * 64 + nt * 8 + (lane >> 2);
                uint32_t bf[2] = { Bb[kk * 260 + n], Bb[(kk + 4) * 260 + n] };
                mma8(acc[0][nt], af[0], bf);
                mma8(acc[1][nt], af[1], bf);
            }
        }
        if (kt < 15) {
            int nb = 1 - buf;
            uint32_t* An = As + nb * (16 * 68);
            uint32_t* Bn = Bs + nb * (16 * 260);
            An[(akq + 0) * 68 + ar] = f2t(va.x);
            An[(akq + 1) * 68 + ar] = f2t(va.y);
            An[(akq + 2) * 68 + ar] = f2t(va.z);
            An[(akq + 3) * 68 + ar] = f2t(va.w);
            #pragma unroll
            for (int j = 0; j < 4; j++) {
                uint4 u;
                u.x = f2t(vb[j].x); u.y = f2t(vb[j].y);
                u.z = f2t(vb[j].z); u.w = f2t(vb[j].w);
                *(uint4*)&Bn[bkr * 260 + bnq + j * 4] = u;
            }
            __syncthreads();
        }
    }

    // epilogue
    #pragma unroll
    for (int mt = 0; mt < 2; mt++) {
        int gr0 = rowBase + wm * 32 + mt * 16 + (lane >> 2);
        #pragma unroll
        for (int nt = 0; nt < 8; nt++) {
            int gc = nBase + wn * 64 + nt * 8 + (lane & 3) * 2;
            #pragma unroll
            for (int h = 0; h < 2; h++) {
                int gr = gr0 + h * 8;
                float v0 = acc[mt][nt][h * 2 + 0];
                float v1 = acc[mt][nt][h * 2 + 1];
                if (blockIdx.y == 0) {
                    *(float2*)&g_H1[(size_t)gr * 256 + gc] = make_float2(v0, v1);
                } else {
                    int f = gc - 256;
                    int n = gr & 63;
                    float o0 = v0 * __ldg(&g_d[f * 64 + n]) + __ldg(&bias[f]);
                    float o1 = v1 * __ldg(&g_d[(f + 1) * 64 + n]) + __ldg(&bias[f + 1]);
                    *(float2*)&out[(size_t)gr * 256 + f] = make_float2(o0, o1);
                }
            }
        }
    }
}

// -------- kernel 4: einsum  out[b,n,f] += sum_m adj[f,n,m] * H1[b,m,f] --------
// CTA: 64 batches x 8 channels. Per f: [64b,64n,64m] GEMM via tf32 mma.
#define EIN_H1S (64 * 516)
#define EIN_ADJ (64 * 68)
#define EIN_SMEM ((EIN_H1S + EIN_ADJ) * 4)

__global__ __launch_bounds__(256, 1) void k_einsum(float* __restrict__ out) {
    float* h1s = sm_dyn;                 // [b][m*8 + fl], row stride 516 (pad)
    float* adjs = sm_dyn + EIN_H1S;      // [n][m], row stride 68 (pad)

    const int t = threadIdx.x, lane = t & 31, w = t >> 5;
    const int wm = w & 1, wn = w >> 1;
    const int B0 = blockIdx.x * 64;
    const int f0 = blockIdx.y * 8;
    const size_t R0 = (size_t)B0 * 64;

    // load H1 tile: 4096 rows x 8 channels (32B/row, sector-aligned)
    #pragma unroll
    for (int i = 0; i < 16; i++) {
        int r = i * 256 + t;
        const float* src = g_H1 + (R0 + r) * 256 + f0;
        float4 u = *(const float4*)src;
        float4 v = *(const float4*)(src + 4);
        float* dst = h1s + (r >> 6) * 516 + (r & 63) * 8;
        *(float4*)dst = u;
        *(float4*)(dst + 4) = v;
    }

    float acc[8][2][2][4];
    #pragma unroll
    for (int a = 0; a < 8; a++)
        #pragma unroll
        for (int b = 0; b < 2; b++)
            #pragma unroll
            for (int c = 0; c < 2; c++)
                #pragma unroll
                for (int r = 0; r < 4; r++) acc[a][b][c][r] = 0.0f;

    #pragma unroll
    for (int fl = 0; fl < 8; fl++) {
        __syncthreads();   // protect adjs from prior readers (and covers h1s at fl=0)
        {
            const float* ab = g_adj + (size_t)(f0 + fl) * 4096;
            int n = t >> 2, mq = (t & 3) * 16;
            #pragma unroll
            for (int j = 0; j < 4; j++) {
                float4 v = *(const float4*)(ab + n * 64 + mq + j * 4);
                *(float4*)(adjs + n * 68 + mq + j * 4) = v;
            }
        }
        __syncthreads();

        #pragma unroll
        for (int ks = 0; ks < 8; ks++) {
            int kk = ks * 8 + (lane & 3);
            uint32_t af[2][4];
            #pragma unroll
            for (int mt = 0; mt < 2; mt++) {
                int b = wm * 32 + mt * 16 + (lane >> 2);
                af[mt][0] = f2t(h1s[(b)     * 516 + kk * 8 + fl]);
                af[mt][1] = f2t(h1s[(b + 8) * 516 + kk * 8 + fl]);
                af[mt][2] = f2t(h1s[(b)     * 516 + (kk + 4) * 8 + fl]);
                af[mt][3] = f2t(h1s[(b + 8) * 516 + (kk + 4) * 8 + fl]);
            }
            #pragma unroll
            for (int nt = 0; nt < 2; nt++) {
                int n = wn * 16 + nt * 8 + (lane >> 2);
                uint32_t bf[2] = { f2t(adjs[n * 68 + kk]), f2t(adjs[n * 68 + kk + 4]) };
                mma8(acc[fl][0][nt], af[0], bf);
                mma8(acc[fl][1][nt], af[1], bf);
            }
        }
    }

    // epilogue: per (b,n) one 32B-sector RMW covering all 8 channels
    #pragma unroll
    for (int mt = 0; mt < 2; mt++) {
        #pragma unroll
        for (int nt = 0; nt < 2; nt++) {
            #pragma unroll
            for (int h = 0; h < 2; h++) {
                int b = wm * 32 + mt * 16 + (lane >> 2) + h * 8;
                #pragma unroll
                for (int q = 0; q < 2; q++) {
                    int n = wn * 16 + nt * 8 + (lane & 3) * 2 + q;
                    float* p = out + ((size_t)(B0 + b) * 64 + n) * 256 + f0;
                    float4 o0 = *(float4*)p;
                    float4 o1 = *(float4*)(p + 4);
                    int r = h * 2 + q;
                    o0.x += acc[0][mt][nt][r];
                    o0.y += acc[1][mt][nt][r];
                    o0.z += acc[2][mt][nt][r];
                    o0.w += acc[3][mt][nt][r];
                    o1.x += acc[4][mt][nt][r];
                    o1.y += acc[5][mt][nt][r];
                    o1.z += acc[6][mt][nt][r];
                    o1.w += acc[7][mt][nt][r];
                    *(float4*)p = o0;
                    *(float4*)(p + 4) = o1;
                }
            }
        }
    }
}

// -------- launch --------
extern "C" void kernel_launch(void* const* d_in, const int* in_sizes, int n_in,
                              void* d_out, int out_size) {
    // Identify inputs by element count (robust to metadata ordering):
    // x=2048*64*256, W=2*256*256, e=256*64*64, bias=256, mask=64*64
    const float* x = nullptr;
    const float* W = nullptr;
    const float* e = nullptr;
    const float* bias = nullptr;
    const void* mask = nullptr;
    for (int i = 0; i < n_in; i++) {
        switch (in_sizes[i]) {
            case 33554432: x = (const float*)d_in[i]; break;
            case 131072:   W = (const float*)d_in[i]; break;
            case 1048576:  e = (const float*)d_in[i]; break;
            case 256:      bias = (const float*)d_in[i]; break;
            case 4096:     mask = d_in[i]; break;
            default: break;
        }
    }
    float* out = (float*)d_out;

    cudaFuncSetAttribute(k_gemm, cudaFuncAttributeMaxDynamicSharedMemorySize, GEMM_SMEM);
    cudaFuncSetAttribute(k_einsum, cudaFuncAttributeMaxDynamicSharedMemorySize, EIN_SMEM);

    k_detect<<<1, 32>>>((const int*)mask);
    k_prep<<<512, 256>>>(W);
    k_softmax<<<2048, 256>>>(e, mask);
    k_gemm<<<dim3(2048, 2), 256, GEMM_SMEM>>>(x, bias, out);
    k_einsum<<<dim3(32, 32), 256, EIN_SMEM>>>(out);
}

// round 4
// speedup vs baseline: 1.3841x; 1.3841x over previous
#include <cuda_runtime.h>
#include <cstdint>
#include <cstddef>

// Problem dims (fixed per reference)
#define BB_ 2048
#define NN_ 64
#define CC_ 256
#define FF_ 256
#define NEGV (-9.0e15f)

// -------- scratch (allocation-free: __device__ globals) --------
__device__ float g_H1[BB_ * NN_ * FF_];      // 134 MB: h1 = x@W1, layout [(b*64+m), f]
__device__ float g_adj[FF_ * NN_ * NN_];     // 4 MB: full softmax adj [f][n][m]
__device__ float g_d[FF_ * NN_];             // diag adj[f][n][n], layout [f][n]
__device__ float g_WcatT[2 * FF_ * CC_];     // transposed: [n=512][c=256]; n<256: W1^T, n>=256: (W0-W1)^T
__device__ int   g_mask_mode;                // 0=uint8, 1=int32, 2=float32

// -------- helpers --------
__device__ __forceinline__ uint32_t f2t(float x) {
    uint32_t r;
    asm("cvt.rna.tf32.f32 %0, %1;" : "=r"(r) : "f"(x));
    return r;
}

__device__ __forceinline__ void mma8(float* d, const uint32_t* a, const uint32_t* b) {
    asm volatile(
        "mma.sync.aligned.m16n8k8.row.col.f32.tf32.tf32.f32 "
        "{%0,%1,%2,%3}, {%4,%5,%6,%7}, {%8,%9}, {%0,%1,%2,%3};\n"
        : "+f"(d[0]), "+f"(d[1]), "+f"(d[2]), "+f"(d[3])
        : "r"(a[0]), "r"(a[1]), "r"(a[2]), "r"(a[3]), "r"(b[0]), "r"(b[1]));
}

__device__ __forceinline__ void ldsm4(uint32_t* r, uint32_t addr) {
    asm volatile("ldmatrix.sync.aligned.m8n8.x4.shared.b16 {%0,%1,%2,%3}, [%4];"
        : "=r"(r[0]), "=r"(r[1]), "=r"(r[2]), "=r"(r[3]) : "r"(addr));
}

// single extern dynamic-smem symbol
extern __shared__ float sm_dyn[];

// -------- kernel 0: detect mask dtype --------
__global__ void k_detect(const int* __restrict__ m) {
    int all01 = 1, allf = 1;
    for (int i = threadIdx.x; i < 1024; i += 32) {
        int v = m[i];
        if (!(v == 0 || v == 1)) all01 = 0;
        if (!(v == 0 || v == 0x3F800000)) allf = 0;
    }
    #pragma unroll
    for (int s = 16; s > 0; s >>= 1) {
        all01 &= __shfl_xor_sync(0xffffffffu, all01, s);
        allf  &= __shfl_xor_sync(0xffffffffu, allf, s);
    }
    if (threadIdx.x == 0) g_mask_mode = all01 ? 1 : (allf ? 2 : 0);
}

// -------- kernel 1: build WcatT[n][c] : n<256 -> W1^T ; n>=256 -> (W0-W1)^T --------
__global__ void k_prep(const float* __restrict__ W) {
    int i = blockIdx.x * 256 + threadIdx.x;     // 131072 = 512*256
    int n = i >> 8, c = i & 255;
    float v;
    if (n < 256) {
        v = W[CC_ * FF_ + c * 256 + n];                           // W1[c][n]
    } else {
        int f = n - 256;
        v = W[c * 256 + f] - W[CC_ * FF_ + c * 256 + f];          // (W0-W1)[c][f]
    }
    g_WcatT[n * 256 + c] = v;
}

// -------- kernel 2: masked row-softmax of e -> adj, diag -> d --------
__global__ void k_softmax(const float* __restrict__ e, const void* __restrict__ maskp) {
    int w = threadIdx.x >> 5, lane = threadIdx.x & 31;
    int row = blockIdx.x * 8 + w;               // 0..16383 (= f*64+n)
    int n = row & 63;

    int mode = g_mask_mode;
    bool m0, m1;
    if (mode == 1) {
        const int* mi = (const int*)maskp;
        m0 = mi[n * 64 + lane] != 0;
        m1 = mi[n * 64 + lane + 32] != 0;
    } else if (mode == 2) {
        const float* mf = (const float*)maskp;
        m0 = mf[n * 64 + lane] != 0.0f;
        m1 = mf[n * 64 + lane + 32] != 0.0f;
    } else {
        const unsigned char* mb = (const unsigned char*)maskp;
        m0 = mb[n * 64 + lane] != 0;
        m1 = mb[n * 64 + lane + 32] != 0;
    }

    const float* er = e + (size_t)row * 64;
    float v0 = m0 ? er[lane] : NEGV;
    float v1 = m1 ? er[lane + 32] : NEGV;

    float mx = fmaxf(v0, v1);
    #pragma unroll
    for (int s = 16; s > 0; s >>= 1) mx = fmaxf(mx, __shfl_xor_sync(0xffffffff, mx, s));

    float e0 = expf(v0 - mx);
    float e1 = expf(v1 - mx);
    float sum = e0 + e1;
    #pragma unroll
    for (int s = 16; s > 0; s >>= 1) sum += __shfl_xor_sync(0xffffffff, sum, s);
    float inv = 1.0f / sum;

    float a0 = e0 * inv, a1 = e1 * inv;
    g_adj[(size_t)row * 64 + lane] = a0;
    g_adj[(size_t)row * 64 + lane + 32] = a1;
    if (lane == n)      g_d[row] = a0;
    if (lane + 32 == n) g_d[row] = a1;
}

// -------- kernel 3: tf32 GEMM  Y = X[131072,256] @ Wcat[256,512], ldmatrix edition --------
// As: [m=64][k=16] stride 20 (tf32 words); Bs: [n=256][k=16] stride 20. Double buffered.
// ldmatrix rows stride 20w=80B -> banks (20i)%32 distinct over 8 rows: conflict-free.
#define ASTR 20
#define GEMM_AW (64 * ASTR)                 // 1280 words
#define GEMM_BW (256 * ASTR)                // 5120 words
#define GEMM_BUFW (GEMM_AW + GEMM_BW)       // 6400 words
#define GEMM_SMEM (2 * GEMM_BUFW * 4)       // 51200 B

__global__ __launch_bounds__(256, 2) void k_gemm(const float* __restrict__ X,
                                                 const float* __restrict__ bias,
                                                 float* __restrict__ out) {
    uint32_t* S = (uint32_t*)sm_dyn;
    const uint32_t sbase = (uint32_t)__cvta_generic_to_shared(sm_dyn);

    const int t = threadIdx.x, lane = t & 31, w = t >> 5;
    const int wm = w & 1, wn = w >> 1;          // 2 x 4 warps; warp tile 32m x 64n
    const int rowBase = blockIdx.x * 64;
    const int nBase = blockIdx.y * 256;

    // loaders
    const int ar = t >> 2, akq = (t & 3) * 4;   // A: row ar, 4 k-words
    const int bn = t >> 2, bj = (t & 3) * 4;    // B: rows bn + 64p, 4 k-words
    const float* gA = X + (size_t)(rowBase + ar) * 256 + akq;
    const float* gB = g_WcatT + (size_t)(nBase + bn) * 256 + bj;

    // ldmatrix lane offsets (in words)
    const int aOff = ((lane & 15) * ASTR) + ((lane >> 4) * 4);                    // A: rows m0..m0+15, col +0/+4
    const int bOff = (((lane & 7) + ((lane >> 4) << 3)) * ASTR) + (((lane >> 3) & 1) * 4); // B: rows n0..n0+15, col +0/+4

    float acc[2][8][4];
    #pragma unroll
    for (int i = 0; i < 2; i++)
        #pragma unroll
        for (int j = 0; j < 8; j++)
            #pragma unroll
            for (int r = 0; r < 4; r++) acc[i][j][r] = 0.0f;

    float4 va, vb[4];

    // prefetch + store stage 0
    va = *(const float4*)(gA);
    #pragma unroll
    for (int p = 0; p < 4; p++) vb[p] = *(const float4*)(gB + p * 64 * 256);
    {
        uint4 u;
        u.x = f2t(va.x); u.y = f2t(va.y); u.z = f2t(va.z); u.w = f2t(va.w);
        *(uint4*)&S[ar * ASTR + akq] = u;
        #pragma unroll
        for (int p = 0; p < 4; p++) {
            uint4 b;
            b.x = f2t(vb[p].x); b.y = f2t(vb[p].y); b.z = f2t(vb[p].z); b.w = f2t(vb[p].w);
            *(uint4*)&S[GEMM_AW + (bn + p * 64) * ASTR + bj] = b;
        }
    }
    __syncthreads();

    #pragma unroll 1
    for (int kt = 0; kt < 16; kt++) {
        const int buf = kt & 1;
        const uint32_t aFragBase = sbase + (buf * GEMM_BUFW + wm * 32 * ASTR + aOff) * 4;
        const uint32_t bFragBase = sbase + (buf * GEMM_BUFW + GEMM_AW + wn * 64 * ASTR + bOff) * 4;

        if (kt < 15) {
            int k0 = (kt + 1) * 16;
            va = *(const float4*)(gA + k0);
            #pragma unroll
            for (int p = 0; p < 4; p++) vb[p] = *(const float4*)(gB + p * 64 * 256 + k0);
        }

        #pragma unroll
        for (int ks = 0; ks < 2; ks++) {
            uint32_t af[2][4];
            ldsm4(af[0], aFragBase + (ks * 8) * 4);
            ldsm4(af[1], aFragBase + (16 * ASTR + ks * 8) * 4);
            #pragma unroll
            for (int ntp = 0; ntp < 4; ntp++) {
                uint32_t bb[4];
                ldsm4(bb, bFragBase + (ntp * 16 * ASTR + ks * 8) * 4);
                mma8(acc[0][2 * ntp + 0], af[0], bb + 0);
                mma8(acc[1][2 * ntp + 0], af[1], bb + 0);
                mma8(acc[0][2 * ntp + 1], af[0], bb + 2);
                mma8(acc[1][2 * ntp + 1], af[1], bb + 2);
            }
        }

        if (kt < 15) {
            const int nb = 1 - buf;
            uint32_t* Sn = S + nb * GEMM_BUFW;
            uint4 u;
            u.x = f2t(va.x); u.y = f2t(va.y); u.z = f2t(va.z); u.w = f2t(va.w);
            *(uint4*)&Sn[ar * ASTR + akq] = u;
            #pragma unroll
            for (int p = 0; p < 4; p++) {
                uint4 b;
                b.x = f2t(vb[p].x); b.y = f2t(vb[p].y); b.z = f2t(vb[p].z); b.w = f2t(vb[p].w);
                *(uint4*)&Sn[GEMM_AW + (bn + p * 64) * ASTR + bj] = b;
            }
            __syncthreads();
        }
    }

    // epilogue: acc[mt][nt] -> rows rowBase+wm*32+mt*16+t/4(+8), cols nBase+wn*64+nt*8+2*(t%4)(+1)
    #pragma unroll
    for (int mt = 0; mt < 2; mt++) {
        int gr0 = rowBase + wm * 32 + mt * 16 + (lane >> 2);
        #pragma unroll
        for (int nt = 0; nt < 8; nt++) {
            int gc = nBase + wn * 64 + nt * 8 + (lane & 3) * 2;
            #pragma unroll
            for (int h = 0; h < 2; h++) {
                int gr = gr0 + h * 8;
                float v0 = acc[mt][nt][h * 2 + 0];
                float v1 = acc[mt][nt][h * 2 + 1];
                if (blockIdx.y == 0) {
                    *(float2*)&g_H1[(size_t)gr * 256 + gc] = make_float2(v0, v1);
                } else {
                    int f = gc - 256;
                    int n = gr & 63;
                    float o0 = v0 * __ldg(&g_d[f * 64 + n]) + __ldg(&bias[f]);
                    float o1 = v1 * __ldg(&g_d[(f + 1) * 64 + n]) + __ldg(&bias[f + 1]);
                    *(float2*)&out[(size_t)gr * 256 + f] = make_float2(o0, o1);
                }
            }
        }
    }
}

// -------- kernel 4: einsum  out[b,n,f] += sum_m adj[f,n,m] * H1[b,m,f] --------
// planes[fl][b=64][m=64] tf32 (stride 68, conflict-free LDSM), adj double-buffered [n=64][m=64] tf32.
#define PSTR 68
#define EIN_PLANEW (64 * PSTR)                  // 4352 words per plane
#define EIN_PLANES_W (8 * EIN_PLANEW)           // 34816 words
#define EIN_ADJW EIN_PLANEW                     // 4352 words per adj buffer
#define EIN_SMEM ((EIN_PLANES_W + 2 * EIN_ADJW) * 4)   // 174080 B

__global__ __launch_bounds__(256, 1) void k_einsum(float* __restrict__ out) {
    uint32_t* P = (uint32_t*)sm_dyn;                    // planes
    uint32_t* ADJ = (uint32_t*)sm_dyn + EIN_PLANES_W;   // 2 buffers
    const uint32_t sbase = (uint32_t)__cvta_generic_to_shared(sm_dyn);

    const int t = threadIdx.x, lane = t & 31, w = t >> 5;
    const int wm = w & 1, wn = w >> 1;      // warp tile: 32 b x 16 n
    const int B0 = blockIdx.x * 64;
    const int f0 = blockIdx.y * 8;
    const size_t R0 = (size_t)B0 * 64;

    const int aOff = ((lane & 15) * PSTR) + ((lane >> 4) * 4);
    const int bOff = (((lane & 7) + ((lane >> 4) << 3)) * PSTR) + (((lane >> 3) & 1) * 4);

    // load H1 tile -> 8 tf32 planes [fl][b][m]
    #pragma unroll
    for (int i = 0; i < 16; i++) {
        int r = i * 256 + t;
        int b = r >> 6, m = r & 63;
        const float* src = g_H1 + (R0 + r) * 256 + f0;
        float4 u = *(const float4*)src;
        float4 v = *(const float4*)(src + 4);
        uint32_t* d = P + b * PSTR + m;
        d[0 * EIN_PLANEW] = f2t(u.x);
        d[1 * EIN_PLANEW] = f2t(u.y);
        d[2 * EIN_PLANEW] = f2t(u.z);
        d[3 * EIN_PLANEW] = f2t(u.w);
        d[4 * EIN_PLANEW] = f2t(v.x);
        d[5 * EIN_PLANEW] = f2t(v.y);
        d[6 * EIN_PLANEW] = f2t(v.z);
        d[7 * EIN_PLANEW] = f2t(v.w);
    }

    float acc[8][2][2][4];
    #pragma unroll
    for (int a = 0; a < 8; a++)
        #pragma unroll
        for (int b = 0; b < 2; b++)
            #pragma unroll
            for (int c = 0; c < 2; c++)
                #pragma unroll
                for (int r = 0; r < 4; r++) acc[a][b][c][r] = 0.0f;

    #pragma unroll
    for (int fl = 0; fl < 8; fl++) {
        // stage adj[f0+fl] into buffer fl&1 (tf32-converted)
        {
            uint32_t* ab = ADJ + (fl & 1) * EIN_ADJW;
            const float* src = g_adj + (size_t)(f0 + fl) * 4096;
            int n = t >> 2, mq = (t & 3) * 16;
            #pragma unroll
            for (int j = 0; j < 4; j++) {
                float4 v = *(const float4*)(src + n * 64 + mq + j * 4);
                uint4 u;
                u.x = f2t(v.x); u.y = f2t(v.y); u.z = f2t(v.z); u.w = f2t(v.w);
                *(uint4*)&ab[n * PSTR + mq + j * 4] = u;
            }
        }
        __syncthreads();   // also covers plane-store completion at fl=0

        const uint32_t aFragBase = sbase + (fl * EIN_PLANEW + wm * 32 * PSTR + aOff) * 4;
        const uint32_t bFragBase = sbase + (EIN_PLANES_W + (fl & 1) * EIN_ADJW + wn * 16 * PSTR + bOff) * 4;

        #pragma unroll
        for (int ks = 0; ks < 8; ks++) {
            uint32_t af[2][4];
            ldsm4(af[0], aFragBase + (ks * 8) * 4);
            ldsm4(af[1], aFragBase + (16 * PSTR + ks * 8) * 4);
            uint32_t bb[4];
            ldsm4(bb, bFragBase + (ks * 8) * 4);
            mma8(acc[fl][0][0], af[0], bb + 0);
            mma8(acc[fl][1][0], af[1], bb + 0);
            mma8(acc[fl][0][1], af[0], bb + 2);
            mma8(acc[fl][1][1], af[1], bb + 2);
        }
    }

    // epilogue: per (b,n) one 32B-sector RMW covering all 8 channels
    #pragma unroll
    for (int mt = 0; mt < 2; mt++) {
        #pragma unroll
        for (int nt = 0; nt < 2; nt++) {
            #pragma unroll
            for (int h = 0; h < 2; h++) {
                int b = wm * 32 + mt * 16 + (lane >> 2) + h * 8;
                #pragma unroll
                for (int q = 0; q < 2; q++) {
                    int n = wn * 16 + nt * 8 + (lane & 3) * 2 + q;
                    float* p = out + ((size_t)(B0 + b) * 64 + n) * 256 + f0;
                    float4 o0 = *(float4*)p;
                    float4 o1 = *(float4*)(p + 4);
                    int r = h * 2 + q;
                    o0.x += acc[0][mt][nt][r];
                    o0.y += acc[1][mt][nt][r];
                    o0.z += acc[2][mt][nt][r];
                    o0.w += acc[3][mt][nt][r];
                    o1.x += acc[4][mt][nt][r];
                    o1.y += acc[5][mt][nt][r];
                    o1.z += acc[6][mt][nt][r];
                    o1.w += acc[7][mt][nt][r];
                    *(float4*)p = o0;
                    *(float4*)(p + 4) = o1;
                }
            }
        }
    }
}

// -------- launch --------
extern "C" void kernel_launch(void* const* d_in, const int* in_sizes, int n_in,
                              void* d_out, int out_size) {
    const float* x = nullptr;
    const float* W = nullptr;
    const float* e = nullptr;
    const float* bias = nullptr;
    const void* mask = nullptr;
    for (int i = 0; i < n_in; i++) {
        switch (in_sizes[i]) {
            case 33554432: x = (const float*)d_in[i]; break;
            case 131072:   W = (const float*)d_in[i]; break;
            case 1048576:  e = (const float*)d_in[i]; break;
            case 256:      bias = (const float*)d_in[i]; break;
            case 4096:     mask = d_in[i]; break;
            default: break;
        }
    }
    float* out = (float*)d_out;

    cudaFuncSetAttribute(k_gemm, cudaFuncAttributeMaxDynamicSharedMemorySize, GEMM_SMEM);
    cudaFuncSetAttribute(k_einsum, cudaFuncAttributeMaxDynamicSharedMemorySize, EIN_SMEM);

    k_detect<<<1, 32>>>((const int*)mask);
    k_prep<<<512, 256>>>(W);
    k_softmax<<<2048, 256>>>(e, mask);
    k_gemm<<<dim3(2048, 2), 256, GEMM_SMEM>>>(x, bias, out);
    k_einsum<<<dim3(32, 32), 256, EIN_SMEM>>>(out);
}

// round 6
// speedup vs baseline: 1.5186x; 1.0972x over previous
#include <cuda_runtime.h>
#include <cstdint>
#include <cstddef>

// Problem dims (fixed per reference)
#define BB_ 2048
#define NN_ 64
#define CC_ 256
#define FF_ 256
#define NEGV (-9.0e15f)

// -------- scratch (allocation-free: __device__ globals) --------
__device__ uint32_t g_H1[BB_ * NN_ * FF_];   // 134 MB: h1 as tf32 bits, [(b*64+m), f]
__device__ uint32_t g_adj[FF_ * NN_ * NN_];  // 4 MB: softmax adj as tf32 bits [f][n][m]
__device__ float    g_dT[NN_ * FF_];         // diag, transposed [n][f], f32
__device__ uint32_t g_WT[2 * FF_ * CC_];     // WcatT as tf32 bits [n=512][c=256]
__device__ int      g_mask_mode;             // 0=uint8, 1=int32, 2=float32

// -------- helpers --------
__device__ __forceinline__ uint32_t f2t(float x) {
    uint32_t r;
    asm("cvt.rna.tf32.f32 %0, %1;" : "=r"(r) : "f"(x));
    return r;
}

__device__ __forceinline__ void mma8(float* d, const uint32_t* a, const uint32_t* b) {
    asm volatile(
        "mma.sync.aligned.m16n8k8.row.col.f32.tf32.tf32.f32 "
        "{%0,%1,%2,%3}, {%4,%5,%6,%7}, {%8,%9}, {%0,%1,%2,%3};\n"
        : "+f"(d[0]), "+f"(d[1]), "+f"(d[2]), "+f"(d[3])
        : "r"(a[0]), "r"(a[1]), "r"(a[2]), "r"(a[3]), "r"(b[0]), "r"(b[1]));
}

__device__ __forceinline__ void ldsm4(uint32_t* r, uint32_t addr) {
    asm volatile("ldmatrix.sync.aligned.m8n8.x4.shared.b16 {%0,%1,%2,%3}, [%4];"
        : "=r"(r[0]), "=r"(r[1]), "=r"(r[2]), "=r"(r[3]) : "r"(addr));
}

__device__ __forceinline__ void cpa16(uint32_t dst, const void* src) {
    asm volatile("cp.async.cg.shared.global [%0], [%1], 16;" :: "r"(dst), "l"(src) : "memory");
}
__device__ __forceinline__ void cp_commit() {
    asm volatile("cp.async.commit_group;" ::: "memory");
}
__device__ __forceinline__ void cp_wait0() {
    asm volatile("cp.async.wait_group 0;" ::: "memory");
}

extern __shared__ float sm_dyn[];

// -------- kernel 0: detect mask dtype --------
__global__ void k_detect(const int* __restrict__ m) {
    int all01 = 1, allf = 1;
    for (int i = threadIdx.x; i < 1024; i += 32) {
        int v = m[i];
        if (!(v == 0 || v == 1)) all01 = 0;
        if (!(v == 0 || v == 0x3F800000)) allf = 0;
    }
    #pragma unroll
    for (int s = 16; s > 0; s >>= 1) {
        all01 &= __shfl_xor_sync(0xffffffffu, all01, s);
        allf  &= __shfl_xor_sync(0xffffffffu, allf, s);
    }
    if (threadIdx.x == 0) g_mask_mode = all01 ? 1 : (allf ? 2 : 0);
}

// -------- kernel 1: WT[n][c] tf32: n<256 -> W1^T ; n>=256 -> (W0-W1)^T --------
__global__ void k_prep(const float* __restrict__ W) {
    int i = blockIdx.x * 256 + threadIdx.x;     // 131072 = 512*256
    int n = i >> 8, c = i & 255;
    float v;
    if (n < 256) {
        v = W[CC_ * FF_ + c * 256 + n];
    } else {
        int f = n - 256;
        v = W[c * 256 + f] - W[CC_ * FF_ + c * 256 + f];
    }
    g_WT[i] = f2t(v);
}

// -------- kernel 2: masked row-softmax -> adj (tf32 bits), diag -> dT (f32) --------
__global__ void k_softmax(const float* __restrict__ e, const void* __restrict__ maskp) {
    int w = threadIdx.x >> 5, lane = threadIdx.x & 31;
    int row = blockIdx.x * 8 + w;               // f*64+n
    int n = row & 63;

    int mode = g_mask_mode;
    bool m0, m1;
    if (mode == 1) {
        const int* mi = (const int*)maskp;
        m0 = mi[n * 64 + lane] != 0;
        m1 = mi[n * 64 + lane + 32] != 0;
    } else if (mode == 2) {
        const float* mf = (const float*)maskp;
        m0 = mf[n * 64 + lane] != 0.0f;
        m1 = mf[n * 64 + lane + 32] != 0.0f;
    } else {
        const unsigned char* mb = (const unsigned char*)maskp;
        m0 = mb[n * 64 + lane] != 0;
        m1 = mb[n * 64 + lane + 32] != 0;
    }

    const float* er = e + (size_t)row * 64;
    float v0 = m0 ? er[lane] : NEGV;
    float v1 = m1 ? er[lane + 32] : NEGV;

    float mx = fmaxf(v0, v1);
    #pragma unroll
    for (int s = 16; s > 0; s >>= 1) mx = fmaxf(mx, __shfl_xor_sync(0xffffffff, mx, s));

    float e0 = expf(v0 - mx);
    float e1 = expf(v1 - mx);
    float sum = e0 + e1;
    #pragma unroll
    for (int s = 16; s > 0; s >>= 1) sum += __shfl_xor_sync(0xffffffff, sum, s);
    float inv = 1.0f / sum;

    float a0 = e0 * inv, a1 = e1 * inv;
    g_adj[(size_t)row * 64 + lane] = f2t(a0);
    g_adj[(size_t)row * 64 + lane + 32] = f2t(a1);
    int f = row >> 6;
    if (lane == n)      g_dT[n * 256 + f] = a0;
    if (lane + 32 == n) g_dT[n * 256 + f] = a1;
}

// -------- kernel 3: tf32 GEMM  Y = X[131072,256] @ Wcat[256,512] --------
// BM=128, BN=256, BK=16; 512 thr, 16 warps (4m x 4n), warp tile 32x64.
// A: [m=128][k=16w] 64B rows, swizzle c^=((m>>1)&3); LDG+cvt+STS.
// B: [n=256][k=16w] 64B rows, same swizzle; pre-tf32 via cp.async.
// by==0 -> H1 (tf32 bits); by==1 -> out = dT*(h0-h1)+bias.
#define GEMM_AB 8192
#define GEMM_BB 16384
#define GEMM_BUF (GEMM_AB + GEMM_BB)
#define GEMM_SMEM (2 * GEMM_BUF)          // 49152 B

__global__ __launch_bounds__(512, 1) void k_gemm(const float* __restrict__ X,
                                                 const float* __restrict__ bias,
                                                 float* __restrict__ out) {
    char* smc = (char*)sm_dyn;
    const uint32_t sbase = (uint32_t)__cvta_generic_to_shared(sm_dyn);

    const int t = threadIdx.x, lane = t & 31, w = t >> 5;
    const int wm = w & 3, wn = w >> 2;
    const int rowBase = blockIdx.x * 128;
    const int nB = blockIdx.y * 256;

    // loaders
    const int ar = t >> 2, ac = t & 3;                  // A: row ar, chunk ac
    const int bn = t >> 1, bc0 = (t & 1) * 2;           // B: row bn, chunks bc0, bc0+1
    const float* gA = X + (size_t)(rowBase + ar) * 256 + ac * 4;
    const uint32_t* gB = g_WT + (size_t)(nB + bn) * 256 + bc0 * 4;
    const uint32_t aSts = (uint32_t)(ar * 64 + ((ac ^ ((ar >> 1) & 3)) * 16));
    const uint32_t bD0 = (uint32_t)(bn * 64 + ((bc0 ^ ((bn >> 1) & 3)) * 16));
    const uint32_t bD1 = (uint32_t)(bn * 64 + (((bc0 + 1) ^ ((bn >> 1) & 3)) * 16));

    // ldmatrix lane geometry
    const int amr = lane & 15, akh = lane >> 4;                       // A: row-in-16, k-half
    const int bnr = (lane & 7) + ((lane >> 4) << 3), bkh = (lane >> 3) & 1;

    float acc[2][8][4];
    #pragma unroll
    for (int i = 0; i < 2; i++)
        #pragma unroll
        for (int j = 0; j < 8; j++)
            #pragma unroll
            for (int r = 0; r < 4; r++) acc[i][j][r] = 0.0f;

    // prologue: B0 via cp.async, A0 via LDG+cvt+STS
    float4 va = __ldg((const float4*)gA);
    cpa16(sbase + GEMM_AB + bD0, gB);
    cpa16(sbase + GEMM_AB + bD1, gB + 4);
    cp_commit();
    {
        uint4 u;
        u.x = f2t(va.x); u.y = f2t(va.y); u.z = f2t(va.z); u.w = f2t(va.w);
        *(uint4*)(smc + aSts) = u;
    }

    #pragma unroll 1
    for (int kt = 0; kt < 16; kt++) {
        const int b = kt & 1;
        const uint32_t abase = sbase + b * GEMM_BUF;
        const uint32_t bbase = abase + GEMM_AB;

        if (kt < 15) va = __ldg((const float4*)(gA + (kt + 1) * 16));

        cp_wait0();
        __syncthreads();

        if (kt < 15) {
            const uint32_t nbB = sbase + (1 - b) * GEMM_BUF + GEMM_AB;
            const uint32_t* s = gB + (kt + 1) * 16;
            cpa16(nbB + bD0, s);
            cpa16(nbB + bD1, s + 4);
            cp_commit();
        }

        #pragma unroll
        for (int ks = 0; ks < 2; ks++) {
            uint32_t af[2][4];
            #pragma unroll
            for (int mt = 0; mt < 2; mt++) {
                int m = wm * 32 + mt * 16 + amr;
                int c = ks * 2 + akh;
                ldsm4(af[mt], abase + m * 64 + ((c ^ ((m >> 1) & 3)) * 16));
            }
            #pragma unroll
            for (int ntp = 0; ntp < 4; ntp++) {
                int nl = wn * 64 + ntp * 16 + bnr;
                int c = ks * 2 + bkh;
                uint32_t bb[4];
                ldsm4(bb, bbase + nl * 64 + ((c ^ ((nl >> 1) & 3)) * 16));
                mma8(acc[0][2 * ntp + 0], af[0], bb + 0);
                mma8(acc[1][2 * ntp + 0], af[1], bb + 0);
                mma8(acc[0][2 * ntp + 1], af[0], bb + 2);
                mma8(acc[1][2 * ntp + 1], af[1], bb + 2);
            }
        }

        if (kt < 15) {
            uint4 u;
            u.x = f2t(va.x); u.y = f2t(va.y); u.z = f2t(va.z); u.w = f2t(va.w);
            *(uint4*)(smc + (1 - b) * GEMM_BUF + aSts) = u;
        }
    }

    // epilogue
    #pragma unroll
    for (int mt = 0; mt < 2; mt++) {
        int gr0 = rowBase + wm * 32 + mt * 16 + (lane >> 2);
        #pragma unroll
        for (int nt = 0; nt < 8; nt++) {
            int gc = nB + wn * 64 + nt * 8 + (lane & 3) * 2;
            #pragma unroll
            for (int h = 0; h < 2; h++) {
                int gr = gr0 + h * 8;
                float v0 = acc[mt][nt][h * 2 + 0];
                float v1 = acc[mt][nt][h * 2 + 1];
                if (blockIdx.y == 0) {
                    uint2 u = make_uint2(f2t(v0), f2t(v1));
                    *(uint2*)&g_H1[(size_t)gr * 256 + gc] = u;
                } else {
                    int f = gc - 256;
                    int n = gr & 63;
                    float o0 = v0 * __ldg(&g_dT[n * 256 + f]) + __ldg(&bias[f]);
                    float o1 = v1 * __ldg(&g_dT[n * 256 + f + 1]) + __ldg(&bias[f + 1]);
                    *(float2*)&out[(size_t)gr * 256 + f] = make_float2(o0, o1);
                }
            }
        }
    }
}

// -------- kernel 4: einsum  out[b,n,f] += sum_m adj[f,n,m] * H1[b,m,f] --------
// CTA = 64 batches x 4 channels; 8 warps, 2 per channel (b-halves), warp tile 32b x 64n.
// planes[ch][b=64][m=64w] 256B rows, swizzle c^=(b&7); adj[ch][n][m] same, via cp.async.
// Cbuf (f32, reuses adj region) recombines 4 channels for float4 out RMW.
#define EIN_PLANE 16384
#define EIN_PLANES (4 * EIN_PLANE)            // 65536 B
#define EIN_ADJ   (4 * EIN_PLANE)             // 65536 B
#define EIN_SMEM  (EIN_PLANES + EIN_ADJ)      // 131072 B

__global__ __launch_bounds__(256, 1) void k_einsum(float* __restrict__ out) {
    char* smc = (char*)sm_dyn;
    const uint32_t sbase = (uint32_t)__cvta_generic_to_shared(sm_dyn);

    const int t = threadIdx.x, lane = t & 31, w = t >> 5;
    const int ch = w >> 1, bh = w & 1;          // warp's channel + b-half
    const int f0 = blockIdx.x * 4;
    const int B0 = blockIdx.y * 64;
    const size_t R0 = (size_t)B0 * 64;

    // ---- stage planes: 4096 H1 rows x 4 channels (tf32 bits) ----
    #pragma unroll
    for (int i = 0; i < 16; i++) {
        int r = i * 256 + t;
        int b = r >> 6, m = r & 63;
        uint4 u = __ldg((const uint4*)(g_H1 + (R0 + r) * 256 + f0));
        uint32_t wbase = b * 64 + ((m >> 2) ^ (b & 7)) * 4 + (m & 3);
        *(uint32_t*)(smc + 0 * EIN_PLANE + wbase * 4) = u.x;
        *(uint32_t*)(smc + 1 * EIN_PLANE + wbase * 4) = u.y;
        *(uint32_t*)(smc + 2 * EIN_PLANE + wbase * 4) = u.z;
        *(uint32_t*)(smc + 3 * EIN_PLANE + wbase * 4) = u.w;
    }
    // ---- stage adj via cp.async: 4 channels x 64 n x 16 chunks ----
    #pragma unroll
    for (int j = 0; j < 16; j++) {
        int idx = j * 256 + t;
        int c4 = idx >> 10, rem = idx & 1023;
        int n = rem >> 4, c = rem & 15;
        const uint32_t* src = g_adj + (size_t)(f0 + c4) * 4096 + n * 64 + c * 4;
        uint32_t dst = sbase + EIN_PLANES + c4 * EIN_PLANE + n * 256 + ((c ^ (n & 7)) * 16);
        cpa16(dst, src);
    }
    cp_commit();
    cp_wait0();
    __syncthreads();

    // ---- mma: each warp = one channel, tile 32b x 64n over k=64 ----
    const uint32_t pbase = sbase + ch * EIN_PLANE;
    const uint32_t jbase = sbase + EIN_PLANES + ch * EIN_PLANE;
    const int amr = lane & 15, akh = lane >> 4;
    const int bnr = (lane & 7) + ((lane >> 4) << 3), bkh = (lane >> 3) & 1;

    float acc[2][8][4];
    #pragma unroll
    for (int i = 0; i < 2; i++)
        #pragma unroll
        for (int j = 0; j < 8; j++)
            #pragma unroll
            for (int r = 0; r < 4; r++) acc[i][j][r] = 0.0f;

    #pragma unroll
    for (int ks = 0; ks < 8; ks++) {
        uint32_t af[2][4];
        #pragma unroll
        for (int mt = 0; mt < 2; mt++) {
            int b = bh * 32 + mt * 16 + amr;
            int c = ks * 2 + akh;
            ldsm4(af[mt], pbase + b * 256 + ((c ^ (b & 7)) * 16));
        }
        #pragma unroll
        for (int ntp = 0; ntp < 4; ntp++) {
            int n = ntp * 16 + bnr;
            int c = ks * 2 + bkh;
            uint32_t bb[4];
            ldsm4(bb, jbase + n * 256 + ((c ^ (n & 7)) * 16));
            mma8(acc[0][2 * ntp + 0], af[0], bb + 0);
            mma8(acc[1][2 * ntp + 0], af[1], bb + 0);
            mma8(acc[0][2 * ntp + 1], af[0], bb + 2);
            mma8(acc[1][2 * ntp + 1], af[1], bb + 2);
        }
    }
    __syncthreads();   // all adj reads done; safe to overwrite adj region with Cbuf

    // ---- write acc -> Cbuf[ch][b][n] (f32, XOR-swizzled cols) ----
    float* Cbuf = (float*)(smc + EIN_PLANES);
    #pragma unroll
    for (int mt = 0; mt < 2; mt++) {
        #pragma unroll
        for (int h = 0; h < 2; h++) {
            int b = bh * 32 + mt * 16 + (lane >> 2) + h * 8;
            #pragma unroll
            for (int nt = 0; nt < 8; nt++) {
                int col = nt * 8 + (lane & 3) * 2;
                int colp = col ^ ((b & 3) << 3);
                *(float2*)&Cbuf[ch * 4096 + b * 64 + colp] =
                    make_float2(acc[mt][nt][h * 2 + 0], acc[mt][nt][h * 2 + 1]);
            }
        }
    }
    __syncthreads();

    // ---- final RMW: thread -> (b, 16 n's), float4 covering 4 channels ----
    {
        int b = t >> 2;
        int nb0 = (t & 3) * 16;
        #pragma unroll
        for (int i = 0; i < 16; i++) {
            int n = nb0 + i;
            int colp = n ^ ((b & 3) << 3);
            float c0 = Cbuf[0 * 4096 + b * 64 + colp];
            float c1 = Cbuf[1 * 4096 + b * 64 + colp];
            float c2 = Cbuf[2 * 4096 + b * 64 + colp];
            float c3 = Cbuf[3 * 4096 + b * 64 + colp];
            float* p = out + ((size_t)(B0 + b) * 64 + n) * 256 + f0;
            float4 o = *(float4*)p;
            o.x += c0; o.y += c1; o.z += c2; o.w += c3;
            *(float4*)p = o;
        }
    }
}

// -------- launch --------
extern "C" void kernel_launch(void* const* d_in, const int* in_sizes, int n_in,
                              void* d_out, int out_size) {
    const float* x = nullptr;
    const float* W = nullptr;
    const float* e = nullptr;
    const float* bias = nullptr;
    const void* mask = nullptr;
    for (int i = 0; i < n_in; i++) {
        switch (in_sizes[i]) {
            case 33554432: x = (const float*)d_in[i]; break;
            case 131072:   W = (const float*)d_in[i]; break;
            case 1048576:  e = (const float*)d_in[i]; break;
            case 256:      bias = (const float*)d_in[i]; break;
            case 4096:     mask = d_in[i]; break;
            default: break;
        }
    }
    float* out = (float*)d_out;

    cudaFuncSetAttribute(k_gemm, cudaFuncAttributeMaxDynamicSharedMemorySize, GEMM_SMEM);
    cudaFuncSetAttribute(k_einsum, cudaFuncAttributeMaxDynamicSharedMemorySize, EIN_SMEM);

    k_detect<<<1, 32>>>((const int*)mask);
    k_prep<<<512, 256>>>(W);
    k_softmax<<<2048, 256>>>(e, mask);
    k_gemm<<<dim3(1024, 2), 512, GEMM_SMEM>>>(x, bias, out);
    k_einsum<<<dim3(64, 32), 256, EIN_SMEM>>>(out);
}